// round 15
// baseline (speedup 1.0000x reference)
#include <cuda_runtime.h>
#include <cuda_fp16.h>
#include <math_constants.h>
#include <cstdint>

#define E_FIXED 32
#define B_FIXED 256
#define NODES_PER_BLK 8        // kernel2: one warp per node
#define MAX_ELS_FIXED 65536
#define EXP_BLOCKS 8192        // 16.78M elements / (256 thr * 8 el)
#define EDGES_PER_BLK 128      // 1M edges / 8192 blocks
#define N_EDGES_FIXED (32768 * E_FIXED)   // 1048576
#define MLP_BATCH 16           // front-batched LDG.128s per group

// 32 MB scratch: exp(element_mars) in fp16. Static __device__ array (no alloc).
__device__ __half g_expm[(size_t)MAX_ELS_FIXED * B_FIXED];
// Edge weights prefetched in kernel 1 (params[pids], fp32, 4 MB).
__device__ float  g_w32[N_EDGES_FIXED];

// ---------------------------------------------------------------------------
// Kernel 1 (round-13 winner, unchanged): each block prefetches its 128 edges'
// weights (latency hidden under the streaming exp work) and converts its
// 2048-element slice of element_mars to the fp16 exp table.
// ---------------------------------------------------------------------------
__global__ __launch_bounds__(256) void build_tables_kernel(
    const float* __restrict__ em,
    const float* __restrict__ params,
    const int*   __restrict__ pids)
{
    const int t = threadIdx.x;

    float wv = 0.0f;
    int   widx = -1;
    if (t < EDGES_PER_BLK) {
        widx = blockIdx.x * EDGES_PER_BLK + t;            // coalesced pids read
        wv   = params[__ldcs(&pids[widx])];               // scattered (L2-hot)
    }

    const size_t i = ((size_t)blockIdx.x * 256 + t) * 8;
    const float4 a = __ldcs(reinterpret_cast<const float4*>(em + i));
    const float4 b = __ldcs(reinterpret_cast<const float4*>(em + i + 4));

    __half2 h[4];
    h[0] = __floats2half2_rn(__expf(a.x), __expf(a.y));
    h[1] = __floats2half2_rn(__expf(a.z), __expf(a.w));
    h[2] = __floats2half2_rn(__expf(b.x), __expf(b.y));
    h[3] = __floats2half2_rn(__expf(b.z), __expf(b.w));

    *reinterpret_cast<uint4*>(g_expm + i) = *reinterpret_cast<const uint4*>(h);

    if (widx >= 0) g_w32[widx] = wv;

    cudaTriggerProgrammaticLaunchCompletion();
}

// ---------------------------------------------------------------------------
// Kernel 2: out[nids[n], :] = log( sum_e w[n,e] * g_expm[cids[n,e], :] )
// One warp per node; lane owns 8 batch columns. fp32 accumulate.
// MLP experiment: 2 groups of 16 FRONT-BATCHED LDG.128s (explicit register
// buffer) instead of unroll-8 — doubles per-warp loads in flight to test
// whether the 37.5us plateau is latency-bound rather than byte-capped.
// ---------------------------------------------------------------------------
__global__ __launch_bounds__(256) void sum_layer_e32_mlp_kernel(
    const int*   __restrict__ nids,
    const int*   __restrict__ cids,
    float*       __restrict__ out)
{
    const int t    = threadIdx.x;
    const int wn   = t >> 5;          // warp index = local node 0..7
    const int lane = t & 31;
    const int boff = lane << 3;       // 8 halves per lane

    // meta.x = cid, meta.y = float bits of w.
    __shared__ int2 meta[NODES_PER_BLK][E_FIXED];

    // Pre-sync: stage cid (pure input) while kernel 1 drains (PDL window).
    const int gi  = blockIdx.x * 256 + t;    // node-major edge index
    const int cid = __ldcs(&cids[gi]);
    meta[wn][lane].x = cid;

    // Wait for kernel 1's tables (g_expm, g_w32) to be complete & visible.
    cudaGridDependencySynchronize();

    meta[wn][lane].y = __float_as_int(g_w32[gi]);   // coalesced, 4 MB total
    __syncwarp();

    const __half* row_base = g_expm + boff;

    float acc0 = 0.f, acc1 = 0.f, acc2 = 0.f, acc3 = 0.f;
    float acc4 = 0.f, acc5 = 0.f, acc6 = 0.f, acc7 = 0.f;

#pragma unroll
    for (int g = 0; g < E_FIXED / MLP_BATCH; ++g) {
        uint4 u[MLP_BATCH];
        float wv[MLP_BATCH];

        // Front-batch: 16 independent LDG.128s issued back-to-back.
#pragma unroll
        for (int e = 0; e < MLP_BATCH; ++e) {
            const int2 m = meta[wn][g * MLP_BATCH + e];
            wv[e] = __int_as_float(m.y);
            u[e]  = *reinterpret_cast<const uint4*>(
                row_base + (size_t)m.x * B_FIXED);
        }

        // Consume.
#pragma unroll
        for (int e = 0; e < MLP_BATCH; ++e) {
            const __half2* hp = reinterpret_cast<const __half2*>(&u[e]);
            const float2 f0 = __half22float2(hp[0]);
            const float2 f1 = __half22float2(hp[1]);
            const float2 f2 = __half22float2(hp[2]);
            const float2 f3 = __half22float2(hp[3]);
            const float w = wv[e];
            acc0 = fmaf(f0.x, w, acc0);
            acc1 = fmaf(f0.y, w, acc1);
            acc2 = fmaf(f1.x, w, acc2);
            acc3 = fmaf(f1.y, w, acc3);
            acc4 = fmaf(f2.x, w, acc4);
            acc5 = fmaf(f2.y, w, acc5);
            acc6 = fmaf(f3.x, w, acc6);
            acc7 = fmaf(f3.y, w, acc7);
        }
    }

    float4 o0, o1;
    o0.x = __logf(fmaxf(acc0, 1e-30f));
    o0.y = __logf(fmaxf(acc1, 1e-30f));
    o0.z = __logf(fmaxf(acc2, 1e-30f));
    o0.w = __logf(fmaxf(acc3, 1e-30f));
    o1.x = __logf(fmaxf(acc4, 1e-30f));
    o1.y = __logf(fmaxf(acc5, 1e-30f));
    o1.z = __logf(fmaxf(acc6, 1e-30f));
    o1.w = __logf(fmaxf(acc7, 1e-30f));

    const int nid = __ldg(&nids[blockIdx.x * NODES_PER_BLK + wn]);
    float* op = out + (size_t)nid * B_FIXED + boff;
    __stcs(reinterpret_cast<float4*>(op),     o0);
    __stcs(reinterpret_cast<float4*>(op + 4), o1);
}

// ---------------------------------------------------------------------------
// Generic fallback (reference-faithful two-pass with max stabilization).
// ---------------------------------------------------------------------------
__global__ void sum_layer_generic_kernel(
    const float* __restrict__ element_mars,
    const float* __restrict__ params,
    const int*   __restrict__ nids,
    const int*   __restrict__ cids,
    const int*   __restrict__ pids,
    float*       __restrict__ out,
    int E, int B)
{
    const int n = blockIdx.x;
    for (int t = threadIdx.x; t < B; t += blockDim.x) {
        float m = -CUDART_INF_F;
        for (int e = 0; e < E; ++e) {
            float x = element_mars[(size_t)cids[(size_t)n * E + e] * B + t];
            m = fmaxf(m, x);
        }
        float s = 0.0f;
        for (int e = 0; e < E; ++e) {
            float x = element_mars[(size_t)cids[(size_t)n * E + e] * B + t];
            float w = params[pids[(size_t)n * E + e]];
            s = fmaf(__expf(x - m), w, s);
        }
        out[(size_t)nids[n] * B + t] = __logf(fmaxf(s, 1e-10f)) + m;
    }
}

extern "C" void kernel_launch(void* const* d_in, const int* in_sizes, int n_in,
                              void* d_out, int out_size)
{
    const float* node_mars    = (const float*)d_in[0];
    const float* element_mars = (const float*)d_in[1];
    const float* params       = (const float*)d_in[2];
    const int*   nids         = (const int*)d_in[3];
    const int*   cids         = (const int*)d_in[4];
    const int*   pids         = (const int*)d_in[5];

    const int N = in_sizes[3];
    const int B = in_sizes[0] / N;
    const int E = in_sizes[4] / N;
    const long long els_total = in_sizes[1];

    float* out = (float*)d_out;

    if (E == E_FIXED && B == B_FIXED &&
        els_total == (long long)MAX_ELS_FIXED * B_FIXED &&
        N * E_FIXED == N_EDGES_FIXED &&
        (N % NODES_PER_BLK) == 0 &&
        (size_t)N * B == (size_t)out_size) {
        build_tables_kernel<<<EXP_BLOCKS, 256>>>(element_mars, params, pids);

        // PDL: kernel 2 starts (cid staging) while kernel 1 drains;
        // gridDependencySynchronize gates the table + w32 reads.
        cudaLaunchConfig_t cfg = {};
        cfg.gridDim  = dim3(N / NODES_PER_BLK);
        cfg.blockDim = dim3(256);
        cfg.dynamicSmemBytes = 0;
        cfg.stream = 0;
        cudaLaunchAttribute attrs[1];
        attrs[0].id = cudaLaunchAttributeProgrammaticStreamSerialization;
        attrs[0].val.programmaticStreamSerializationAllowed = 1;
        cfg.attrs = attrs;
        cfg.numAttrs = 1;
        cudaLaunchKernelEx(&cfg, sum_layer_e32_mlp_kernel, nids, cids, out);
    } else {
        cudaMemcpyAsync(out, node_mars, sizeof(float) * (size_t)out_size,
                        cudaMemcpyDeviceToDevice);
        int threads = (B < 256) ? B : 256;
        sum_layer_generic_kernel<<<N, threads>>>(element_mars, params, nids, cids,
                                                 pids, out, E, B);
    }
}